// round 1
// baseline (speedup 1.0000x reference)
#include <cuda_runtime.h>

// Problem constants (fixed-shape problem)
#define NN       10000      // nodes
#define NBATCH   32
#define AS       8
#define NE       320000
#define XSTRIDE  (NN * AS)  // 80000 floats per batch row of x / out

// ---------------- device scratch (no allocations allowed) ----------------
__device__ int g_counts[NN];
__device__ int g_starts[NN + 1];
__device__ int g_cursor[NN];
__device__ int g_perm[NE];
__device__ int g_colp[NE];

// ---------------- CSR build ----------------
__global__ void zero_counts_kernel() {
    int i = blockIdx.x * blockDim.x + threadIdx.x;
    if (i < NN) g_counts[i] = 0;
}

__global__ void hist_kernel(const int* __restrict__ rows) {
    int i = blockIdx.x * blockDim.x + threadIdx.x;
    if (i < NE) atomicAdd(&g_counts[rows[i]], 1);
}

// Single-block exclusive scan of g_counts -> g_starts (NN+1), also seeds g_cursor.
__global__ void scan_kernel() {
    __shared__ int wsum[32];
    const int CHK = 10;                       // 1024 * 10 >= 10000
    int tid  = threadIdx.x;
    int base = tid * CHK;

    int loc[CHK];
    int run = 0;
#pragma unroll
    for (int k = 0; k < CHK; k++) {
        int idx = base + k;
        int v = (idx < NN) ? g_counts[idx] : 0;
        loc[k] = run;
        run += v;
    }

    int lane = tid & 31, wid = tid >> 5;
    int inc = run;
#pragma unroll
    for (int o = 1; o < 32; o <<= 1) {
        int y = __shfl_up_sync(0xffffffffu, inc, o);
        if (lane >= o) inc += y;
    }
    if (lane == 31) wsum[wid] = inc;
    __syncthreads();
    if (wid == 0) {
        int w = wsum[lane];
#pragma unroll
        for (int o = 1; o < 32; o <<= 1) {
            int y = __shfl_up_sync(0xffffffffu, w, o);
            if (lane >= o) w += y;
        }
        wsum[lane] = w;
    }
    __syncthreads();

    int thread_excl = (inc - run) + (wid > 0 ? wsum[wid - 1] : 0);
#pragma unroll
    for (int k = 0; k < CHK; k++) {
        int idx = base + k;
        if (idx < NN) {
            int st = thread_excl + loc[k];
            g_starts[idx] = st;
            g_cursor[idx] = st;
        }
    }
    if (tid == blockDim.x - 1) g_starts[NN] = thread_excl + run;
}

__global__ void scatter_kernel(const int* __restrict__ rows,
                               const int* __restrict__ cols) {
    int i = blockIdx.x * blockDim.x + threadIdx.x;
    if (i < NE) {
        int r = rows[i];
        int p = atomicAdd(&g_cursor[r], 1);
        g_perm[p] = i;
        g_colp[p] = cols[i];
    }
}

// ---------------- compute: one block per output row ----------------
// 128 threads: j = tid & 7 (output column within 8x8 block),
//              bp = tid >> 3 (0..15); thread owns batches {bp, bp+16}.
#define CH 8  // edges staged per chunk

__global__ __launch_bounds__(128) void compute_kernel(
    const float* __restrict__ x,
    const float* __restrict__ values,
    const float* __restrict__ bias,
    float* __restrict__ out)
{
    __shared__ float sv[CH][64];
    __shared__ int   sc[CH];

    int r   = blockIdx.x;
    int tid = threadIdx.x;
    int j   = tid & 7;
    int bp  = tid >> 3;

    int s    = g_starts[r];
    int eend = g_starts[r + 1];

    const float* x0 = x + (long)bp * XSTRIDE;
    const float* x1 = x + (long)(bp + 16) * XSTRIDE;

    float acc0 = 0.0f, acc1 = 0.0f;

    for (int cs = s; cs < eend; cs += CH) {
        int nch = min(CH, eend - cs);

        // stage values: nch * 64 floats; 16 threads * float4 per edge.
        {
            int ei = tid >> 4;          // 0..7 edge slot
            int fi = (tid & 15) * 4;    // 0..60
            if (ei < nch) {
                const float4* src = (const float4*)(values + (long)g_perm[cs + ei] * 64 + fi);
                float4 v = __ldcs(src);            // streaming: don't thrash x out of L2
                *(float4*)&sv[ei][fi] = v;
            }
            if (tid < nch) sc[tid] = g_colp[cs + tid];
        }
        __syncthreads();

        for (int k = 0; k < nch; k++) {
            int c = sc[k] * 8;
            float4 a0 = __ldg((const float4*)(x0 + c));
            float4 a1 = __ldg((const float4*)(x0 + c + 4));
            float4 b0 = __ldg((const float4*)(x1 + c));
            float4 b1 = __ldg((const float4*)(x1 + c + 4));

            const float* vv = &sv[k][j];
            float v0 = vv[0],  v1 = vv[8],  v2 = vv[16], v3 = vv[24];
            float v4 = vv[32], v5 = vv[40], v6 = vv[48], v7 = vv[56];

            acc0 += a0.x * v0 + a0.y * v1 + a0.z * v2 + a0.w * v3
                  + a1.x * v4 + a1.y * v5 + a1.z * v6 + a1.w * v7;
            acc1 += b0.x * v0 + b0.y * v1 + b0.z * v2 + b0.w * v3
                  + b1.x * v4 + b1.y * v5 + b1.z * v6 + b1.w * v7;
        }
        __syncthreads();
    }

    int o = r * 8 + j;
    float bb = __ldg(bias + o);
    out[(long)bp        * XSTRIDE + o] = acc0 + bb;
    out[(long)(bp + 16) * XSTRIDE + o] = acc1 + bb;
}

// ---------------- launch ----------------
extern "C" void kernel_launch(void* const* d_in, const int* in_sizes, int n_in,
                              void* d_out, int out_size)
{
    const float* x      = (const float*)d_in[0];   // (32, 80000, 1)
    const float* values = (const float*)d_in[1];   // (320000, 8, 8)
    const float* bias   = (const float*)d_in[2];   // (80000,)
    const int*   idx    = (const int*)d_in[3];     // (2, 320000)
    float*       out    = (float*)d_out;           // (32, 80000, 1)

    const int* rows = idx;       // indices[0]
    const int* cols = idx + NE;  // indices[1]

    zero_counts_kernel<<<(NN + 255) / 256, 256>>>();
    hist_kernel<<<(NE + 255) / 256, 256>>>(rows);
    scan_kernel<<<1, 1024>>>();
    scatter_kernel<<<(NE + 255) / 256, 256>>>(rows, cols);
    compute_kernel<<<NN, 128>>>(x, values, bias, out);
}

// round 2
// speedup vs baseline: 1.2423x; 1.2423x over previous
#include <cuda_runtime.h>

#define NN 10000
#define NB 32
#define AS 8
#define NE 320000
#define XS (NN*AS)   // 80000 floats per batch

// ---------------- device scratch ----------------
__device__ int   g_counts[NN];
__device__ int   g_starts[NN + 1];
__device__ int   g_cursor[NN];
__device__ int   g_perm[NE];
__device__ int   g_colp[NE];
__device__ float g_xc[NN * NB * AS];   // xc[c][b][i] : 1KB contiguous per node c

// ---------------- helpers ----------------
union F4 { float4 f; ulonglong2 u; };
union U64F2 { unsigned long long u; float2 f; };

__device__ __forceinline__ void ffma2(unsigned long long& d,
                                      unsigned long long a,
                                      unsigned long long b) {
    asm volatile("fma.rn.f32x2 %0, %1, %2, %0;" : "+l"(d) : "l"(a), "l"(b));
}

__device__ __forceinline__ void cp16(void* sdst, const void* gsrc) {
    unsigned sa = (unsigned)__cvta_generic_to_shared(sdst);
    asm volatile("cp.async.cg.shared.global [%0], [%1], 16;" :: "r"(sa), "l"(gsrc));
}
__device__ __forceinline__ void cp_commit() {
    asm volatile("cp.async.commit_group;" ::: "memory");
}
__device__ __forceinline__ void cp_wait0() {
    asm volatile("cp.async.wait_group 0;" ::: "memory");
}

// ---------------- 1) x transpose: x[b][c*8+i] -> xc[c][b*8+i] ----------------
__global__ void transpose_kernel(const float* __restrict__ x) {
    int c = blockIdx.x * 256 + threadIdx.x;
    int b = blockIdx.y;
    if (c < NN) {
        const float4* src = (const float4*)(x + (long)b * XS + c * 8);
        float4 v0 = __ldg(src);
        float4 v1 = __ldg(src + 1);
        float4* dst = (float4*)(g_xc + c * 256 + b * 8);
        dst[0] = v0;
        dst[1] = v1;
    }
}

// ---------------- 2) zero counts ----------------
// NOTE: counts are also re-zeroed at the end of scatter_kernel, and the static
// initializer zeroes them for the very first call; this kernel keeps the
// invariant robust regardless of call history (and keeps launch count at 6).
__global__ void zero_counts_kernel() {
    int i = blockIdx.x * blockDim.x + threadIdx.x;
    if (i < NN) g_counts[i] = 0;
}

// ---------------- 3) histogram (4 edges / thread) ----------------
__global__ void hist_kernel(const int* __restrict__ rows) {
    int base = blockIdx.x * 1024 + threadIdx.x;
#pragma unroll
    for (int q = 0; q < 4; q++) {
        int i = base + q * 256;
        if (i < NE) atomicAdd(&g_counts[rows[i]], 1);
    }
}

// ---------------- 4) exclusive scan (single block) ----------------
__global__ void scan_kernel() {
    __shared__ int wsum[32];
    const int CHK = 10;
    int tid  = threadIdx.x;
    int base = tid * CHK;

    int loc[CHK];
    int run = 0;
#pragma unroll
    for (int k = 0; k < CHK; k++) {
        int idx = base + k;
        int v = (idx < NN) ? g_counts[idx] : 0;
        loc[k] = run;
        run += v;
    }

    int lane = tid & 31, wid = tid >> 5;
    int inc = run;
#pragma unroll
    for (int o = 1; o < 32; o <<= 1) {
        int y = __shfl_up_sync(0xffffffffu, inc, o);
        if (lane >= o) inc += y;
    }
    if (lane == 31) wsum[wid] = inc;
    __syncthreads();
    if (wid == 0) {
        int w = wsum[lane];
#pragma unroll
        for (int o = 1; o < 32; o <<= 1) {
            int y = __shfl_up_sync(0xffffffffu, w, o);
            if (lane >= o) w += y;
        }
        wsum[lane] = w;
    }
    __syncthreads();

    int thread_excl = (inc - run) + (wid > 0 ? wsum[wid - 1] : 0);
#pragma unroll
    for (int k = 0; k < CHK; k++) {
        int idx = base + k;
        if (idx < NN) {
            int st = thread_excl + loc[k];
            g_starts[idx] = st;
            g_cursor[idx] = st;
        }
    }
    if (tid == blockDim.x - 1) g_starts[NN] = thread_excl + run;
}

// ---------------- 5) scatter (4 edges / thread) + re-zero counts ----------------
__global__ void scatter_kernel(const int* __restrict__ rows,
                               const int* __restrict__ cols) {
    int base = blockIdx.x * 1024 + threadIdx.x;
    int r[4], c[4];
#pragma unroll
    for (int q = 0; q < 4; q++) {
        int i = base + q * 256;
        if (i < NE) { r[q] = rows[i]; c[q] = cols[i]; }
    }
    int p[4];
#pragma unroll
    for (int q = 0; q < 4; q++) {
        int i = base + q * 256;
        if (i < NE) p[q] = atomicAdd(&g_cursor[r[q]], 1);
    }
#pragma unroll
    for (int q = 0; q < 4; q++) {
        int i = base + q * 256;
        if (i < NE) { g_perm[p[q]] = i; g_colp[p[q]] = c[q]; }
    }
    // re-zero counts for the next call (scan already consumed them)
    int gid = blockIdx.x * blockDim.x + threadIdx.x;
    if (gid < NN) g_counts[gid] = 0;
}

// ---------------- 6) compute: one block per output row ----------------
// 128 threads: j = tid&7 (output column), bp = tid>>3 (0..15) owns batches {bp, bp+16}.
#define CH 8

// values staged transposed with bank skew: sv[k][joff(j)+i] = v[i][j],
// joff(j) = j*8 + (j&4)  (max index 67 -> row = 68 floats, 16B-aligned rows)
#define VROW 68

__global__ __launch_bounds__(128) void compute_kernel(
    const float* __restrict__ values,
    const float* __restrict__ bias,
    float* __restrict__ out)
{
    __shared__ float sx[2][CH][256];
    __shared__ float sv[2][CH][VROW];

    int r   = blockIdx.x;
    int tid = threadIdx.x;
    int j   = tid & 7;
    int bp  = tid >> 3;
    int joff = j * 8 + (j & 4);

    int s = g_starts[r];
    int e = g_starts[r + 1];
    int n = e - s;

    unsigned long long p0 = 0ull, p1 = 0ull;   // (0.f,0.f) pairs

    // staging roles
    int se = tid >> 4;      // edge slot 0..7
    int sm = tid & 15;      // 16B chunk / float4 index
    int vi = sm >> 1;       // value row i for this thread's float4
    int vjj = (sm & 1) * 4; // value col base jj in {0,4}

    int nchunks = (n + CH - 1) / CH;

    // ---- prologue: stage chunk 0 into buf 0 ----
    if (n > 0) {
        int nch0 = min(CH, n);
        if (se < nch0) {
            int c = __ldg(&g_colp[s + se]);
            const float* src = g_xc + c * 256;
            float* dst = &sx[0][se][0];
#pragma unroll
            for (int q = 0; q < 4; q++)
                cp16(dst + (sm + 16 * q) * 4, src + (sm + 16 * q) * 4);
            int pm = __ldg(&g_perm[s + se]);
            float4 v = __ldcs((const float4*)(values + (long)pm * 64 + sm * 4));
            float* vd = &sv[0][se][0];
            vd[(vjj + 0) * 8 + ((vjj + 0) & 4) + vi] = v.x;
            vd[(vjj + 1) * 8 + ((vjj + 1) & 4) + vi] = v.y;
            vd[(vjj + 2) * 8 + ((vjj + 2) & 4) + vi] = v.z;
            vd[(vjj + 3) * 8 + ((vjj + 3) & 4) + vi] = v.w;
        }
        cp_commit();
    }

    for (int ch = 0; ch < nchunks; ch++) {
        int buf = ch & 1;
        int cs = s + ch * CH;
        int nch = min(CH, e - cs);

        cp_wait0();
        __syncthreads();

        // ---- kick off staging of next chunk ----
        bool have_next = (ch + 1 < nchunks);
        float4 vreg2;
        bool do2 = false;
        if (have_next) {
            int cs2 = cs + CH;
            int nch2 = min(CH, e - cs2);
            do2 = (se < nch2);
            if (do2) {
                int c = __ldg(&g_colp[cs2 + se]);
                const float* src = g_xc + c * 256;
                float* dst = &sx[buf ^ 1][se][0];
#pragma unroll
                for (int q = 0; q < 4; q++)
                    cp16(dst + (sm + 16 * q) * 4, src + (sm + 16 * q) * 4);
                int pm = __ldg(&g_perm[cs2 + se]);
                vreg2 = __ldcs((const float4*)(values + (long)pm * 64 + sm * 4));
            }
            cp_commit();
        }

        // ---- consume current chunk ----
        const float* sxk = &sx[buf][0][0];
        const float* svk = &sv[buf][0][0];
        if (nch == CH) {
#pragma unroll
            for (int k = 0; k < CH; k++) {
                F4 xa0, xa1, xb0, xb1, v0, v1;
                xa0.f = *(const float4*)(sxk + k * 256 + bp * 8);
                xa1.f = *(const float4*)(sxk + k * 256 + bp * 8 + 4);
                xb0.f = *(const float4*)(sxk + k * 256 + (bp + 16) * 8);
                xb1.f = *(const float4*)(sxk + k * 256 + (bp + 16) * 8 + 4);
                v0.f  = *(const float4*)(svk + k * VROW + joff);
                v1.f  = *(const float4*)(svk + k * VROW + joff + 4);
                ffma2(p0, xa0.u.x, v0.u.x);
                ffma2(p1, xb0.u.x, v0.u.x);
                ffma2(p0, xa0.u.y, v0.u.y);
                ffma2(p1, xb0.u.y, v0.u.y);
                ffma2(p0, xa1.u.x, v1.u.x);
                ffma2(p1, xb1.u.x, v1.u.x);
                ffma2(p0, xa1.u.y, v1.u.y);
                ffma2(p1, xb1.u.y, v1.u.y);
            }
        } else {
            for (int k = 0; k < nch; k++) {
                F4 xa0, xa1, xb0, xb1, v0, v1;
                xa0.f = *(const float4*)(sxk + k * 256 + bp * 8);
                xa1.f = *(const float4*)(sxk + k * 256 + bp * 8 + 4);
                xb0.f = *(const float4*)(sxk + k * 256 + (bp + 16) * 8);
                xb1.f = *(const float4*)(sxk + k * 256 + (bp + 16) * 8 + 4);
                v0.f  = *(const float4*)(svk + k * VROW + joff);
                v1.f  = *(const float4*)(svk + k * VROW + joff + 4);
                ffma2(p0, xa0.u.x, v0.u.x);
                ffma2(p1, xb0.u.x, v0.u.x);
                ffma2(p0, xa0.u.y, v0.u.y);
                ffma2(p1, xb0.u.y, v0.u.y);
                ffma2(p0, xa1.u.x, v1.u.x);
                ffma2(p1, xb1.u.x, v1.u.x);
                ffma2(p0, xa1.u.y, v1.u.y);
                ffma2(p1, xb1.u.y, v1.u.y);
            }
        }

        // ---- finish staging next chunk's values (after consume, overlaps LDG) ----
        if (do2) {
            float* vd = &sv[buf ^ 1][se][0];
            vd[(vjj + 0) * 8 + ((vjj + 0) & 4) + vi] = vreg2.x;
            vd[(vjj + 1) * 8 + ((vjj + 1) & 4) + vi] = vreg2.y;
            vd[(vjj + 2) * 8 + ((vjj + 2) & 4) + vi] = vreg2.z;
            vd[(vjj + 3) * 8 + ((vjj + 3) & 4) + vi] = vreg2.w;
        }
    }

    // ---- epilogue: horizontal add pairs, add bias, coalesced store ----
    U64F2 a0, a1;
    a0.u = p0;
    a1.u = p1;
    float r0 = a0.f.x + a0.f.y;
    float r1 = a1.f.x + a1.f.y;
    int o = r * 8 + j;
    float bb = __ldg(&bias[o]);
    out[(long)bp        * XS + o] = r0 + bb;
    out[(long)(bp + 16) * XS + o] = r1 + bb;
}

// ---------------- launch ----------------
extern "C" void kernel_launch(void* const* d_in, const int* in_sizes, int n_in,
                              void* d_out, int out_size)
{
    const float* x      = (const float*)d_in[0];   // (32, 80000, 1)
    const float* values = (const float*)d_in[1];   // (320000, 8, 8)
    const float* bias   = (const float*)d_in[2];   // (80000,)
    const int*   idx    = (const int*)d_in[3];     // (2, 320000)
    float*       out    = (float*)d_out;

    const int* rows = idx;
    const int* cols = idx + NE;

    dim3 tgrid((NN + 255) / 256, NB);
    transpose_kernel<<<tgrid, 256>>>(x);
    zero_counts_kernel<<<(NN + 255) / 256, 256>>>();
    hist_kernel<<<(NE + 1023) / 1024, 256>>>(rows);
    scan_kernel<<<1, 1024>>>();
    scatter_kernel<<<(NE + 1023) / 1024, 256>>>(rows, cols);
    compute_kernel<<<NN, 128>>>(values, bias, out);
}